// round 2
// baseline (speedup 1.0000x reference)
#include <cuda_runtime.h>

// nlwt_catone: fused non-linear wavelet transform
// x: [8, 32, 512, 512] f32  ->  out: [8, 128, 256, 256] f32
//
// out[b, s*32+c, i, j] = sum_k M2[s][k] * a_k where
//   a0 = M1[0] . patch(i, j)
//   a1 = M1[1] . patch((i+1)%H1, j)
//   a2 = M1[2] . patch(i, (j+1)%W1)
//   a3 = M1[3] . patch((i+1)%H1, (j+1)%W1)
// patch(p,q) = [x(2p,2q), x(2p,2q+1), x(2p+1,2q), x(2p+1,2q+1)] within (b,c).
//
// R2: 4 output cols per thread -> STG.128 stores, 12 front-batched loads/thread.

#define Hd   512
#define Wd   512
#define H1d  256
#define W1d  256
#define Cd   32

__device__ __forceinline__ float dot4(float m0, float m1, float m2, float m3,
                                      float p0, float p1, float p2, float p3) {
    return fmaf(m0, p0, fmaf(m1, p1, fmaf(m2, p2, m3 * p3)));
}

__global__ __launch_bounds__(128, 7)
void nlwt_kernel(const float* __restrict__ x, float* __restrict__ out) {
    const int tx   = threadIdx.x;                 // 0..127
    const int lane = tx & 63;                     // 64 threads per output row
    const int i    = blockIdx.x * 2 + (tx >> 6);  // output row 0..255
    const int bc   = blockIdx.y;                  // b*32 + c
    const int j0   = lane * 4;                    // output col (multiple of 4)
    const int c0   = j0 * 2;                      // input col = 8*lane (32B aligned)

    const int i1 = (i + 1 == H1d) ? 0 : i + 1;           // row roll
    const int cn = (j0 + 4 == W1d) ? 0 : c0 + 8;         // col roll (next patch pair)

    const float* base = x + (size_t)bc * (Hd * Wd);
    const float* r0a = base + (size_t)(2 * i)  * Wd;     // row 2i
    const float* r0b = r0a + Wd;                         // row 2i+1
    const float* r1a = base + (size_t)(2 * i1) * Wd;     // row 2*i1
    const float* r1b = r1a + Wd;                         // row 2*i1+1

    // Per source row: 10 floats (8 main + 2 wrap)
    float fa[10], fb[10], fc[10], fd[10];
    {
        float4 v;
        v = *(const float4*)(r0a + c0);     fa[0]=v.x; fa[1]=v.y; fa[2]=v.z; fa[3]=v.w;
        v = *(const float4*)(r0a + c0 + 4); fa[4]=v.x; fa[5]=v.y; fa[6]=v.z; fa[7]=v.w;
        v = *(const float4*)(r0b + c0);     fb[0]=v.x; fb[1]=v.y; fb[2]=v.z; fb[3]=v.w;
        v = *(const float4*)(r0b + c0 + 4); fb[4]=v.x; fb[5]=v.y; fb[6]=v.z; fb[7]=v.w;
        v = *(const float4*)(r1a + c0);     fc[0]=v.x; fc[1]=v.y; fc[2]=v.z; fc[3]=v.w;
        v = *(const float4*)(r1a + c0 + 4); fc[4]=v.x; fc[5]=v.y; fc[6]=v.z; fc[7]=v.w;
        v = *(const float4*)(r1b + c0);     fd[0]=v.x; fd[1]=v.y; fd[2]=v.z; fd[3]=v.w;
        v = *(const float4*)(r1b + c0 + 4); fd[4]=v.x; fd[5]=v.y; fd[6]=v.z; fd[7]=v.w;
        float2 w;
        w = *(const float2*)(r0a + cn);     fa[8]=w.x; fa[9]=w.y;
        w = *(const float2*)(r0b + cn);     fb[8]=w.x; fb[9]=w.y;
        w = *(const float2*)(r1a + cn);     fc[8]=w.x; fc[9]=w.y;
        w = *(const float2*)(r1b + cn);     fd[8]=w.x; fd[9]=w.y;
    }

    // M1 rows:
    //  0.8664  0.1026  0.4852 -0.0574
    // -0.1026  0.8664 -0.0574 -0.4852
    //  0.4852  0.0574 -0.8664  0.1026
    //  0.0574 -0.4852 -0.1026 -0.8664
    // M2 rows:
    //  1.3968  0.2212 -0.2212 -1.3968
    // -0.2212  1.3968 -1.3968  0.2212
    // -0.5412 -1.3066 -1.3066 -0.5412
    //  1.3066 -0.5412 -0.5412  1.3066

    float4 o0, o1, o2, o3;
    float* o0p = &o0.x; float* o1p = &o1.x; float* o2p = &o2.x; float* o3p = &o3.x;

#pragma unroll
    for (int p = 0; p < 4; p++) {
        const int k  = 2 * p;
        const int k2 = k + 2;
        const float a0 = dot4( 0.8664f,  0.1026f,  0.4852f, -0.0574f,
                              fa[k],  fa[k+1],  fb[k],  fb[k+1]);
        const float a1 = dot4(-0.1026f,  0.8664f, -0.0574f, -0.4852f,
                              fc[k],  fc[k+1],  fd[k],  fd[k+1]);
        const float a2 = dot4( 0.4852f,  0.0574f, -0.8664f,  0.1026f,
                              fa[k2], fa[k2+1], fb[k2], fb[k2+1]);
        const float a3 = dot4( 0.0574f, -0.4852f, -0.1026f, -0.8664f,
                              fc[k2], fc[k2+1], fd[k2], fd[k2+1]);

        o0p[p] = dot4( 1.3968f,  0.2212f, -0.2212f, -1.3968f, a0, a1, a2, a3);
        o1p[p] = dot4(-0.2212f,  1.3968f, -1.3968f,  0.2212f, a0, a1, a2, a3);
        o2p[p] = dot4(-0.5412f, -1.3066f, -1.3066f, -0.5412f, a0, a1, a2, a3);
        o3p[p] = dot4( 1.3066f, -0.5412f, -0.5412f,  1.3066f, a0, a1, a2, a3);
    }

    // out[b, s*32 + c, i, j] ; bc = b*32 + c
    const int b = bc >> 5;
    const int c = bc & 31;
    const size_t sband = (size_t)Cd * H1d * W1d;        // stride per subband
    float* op = out + ((size_t)(b * 4 * Cd + c) * H1d + i) * W1d + j0;

    *(float4*)(op)             = o0;
    *(float4*)(op + sband)     = o1;
    *(float4*)(op + 2 * sband) = o2;
    *(float4*)(op + 3 * sband) = o3;
}

extern "C" void kernel_launch(void* const* d_in, const int* in_sizes, int n_in,
                              void* d_out, int out_size) {
    const float* x = (const float*)d_in[0];
    float* out = (float*)d_out;
    dim3 grid(H1d / 2, 8 * Cd);   // (128 row-pairs, 256 bc slices)
    nlwt_kernel<<<grid, 128>>>(x, out);
}

// round 3
// speedup vs baseline: 1.0032x; 1.0032x over previous
#include <cuda_runtime.h>

// nlwt_catone: fused non-linear wavelet transform
// x: [8, 32, 512, 512] f32  ->  out: [8, 128, 256, 256] f32
//
// out[b, s*32+c, i, j] = sum_k M2[s][k] * a_k where
//   a0 = M1[0] . patch(i, j)
//   a1 = M1[1] . patch((i+1)%H1, j)
//   a2 = M1[2] . patch(i, (j+1)%W1)
//   a3 = M1[3] . patch((i+1)%H1, (j+1)%W1)
// patch(p,q) = [x(2p,2q), x(2p,2q+1), x(2p+1,2q), x(2p+1,2q+1)] within (b,c).
//
// R3: R1 layout (best: 2 cols/thread, occ 90%, dram 81.6%) + streaming stores
// (__stcs, evict-first) to keep L2 for the rolled input rows and smooth
// DRAM write drain.

#define Hd   512
#define Wd   512
#define H1d  256
#define W1d  256
#define Cd   32

__device__ __forceinline__ float dot4(float m0, float m1, float m2, float m3,
                                      float p0, float p1, float p2, float p3) {
    return fmaf(m0, p0, fmaf(m1, p1, fmaf(m2, p2, m3 * p3)));
}

__global__ __launch_bounds__(128, 8)
void nlwt_kernel(const float* __restrict__ x, float* __restrict__ out) {
    const int tx = threadIdx.x;        // 0..127
    const int i  = blockIdx.x;         // output row 0..255
    const int bc = blockIdx.y;         // b*32 + c, 0..255
    const int j0 = tx * 2;             // output col (even)
    const int c0 = j0 * 2;             // input col = 4*tx (16B aligned)

    const int i1 = (i + 1 == H1d) ? 0 : i + 1;          // row roll
    const int cn = (j0 + 2 == W1d) ? 0 : c0 + 4;        // col roll (next patch pair)

    const float* base = x + (size_t)bc * (Hd * Wd);
    const float* r0a = base + (size_t)(2 * i)  * Wd;    // row 2i
    const float* r0b = r0a + Wd;                         // row 2i+1
    const float* r1a = base + (size_t)(2 * i1) * Wd;    // row 2*i1
    const float* r1b = r1a + Wd;                         // row 2*i1+1

    // 4x4 (+wrap) input neighborhood, vectorized
    const float4 A  = *(const float4*)(r0a + c0);
    const float4 B  = *(const float4*)(r0b + c0);
    const float4 Cv = *(const float4*)(r1a + c0);
    const float4 D  = *(const float4*)(r1b + c0);
    const float2 A2 = *(const float2*)(r0a + cn);
    const float2 B2 = *(const float2*)(r0b + cn);
    const float2 C2 = *(const float2*)(r1a + cn);
    const float2 D2 = *(const float2*)(r1b + cn);

    // M1 rows (compile-time immediates)
    // row0:  0.8664  0.1026  0.4852 -0.0574
    // row1: -0.1026  0.8664 -0.0574 -0.4852
    // row2:  0.4852  0.0574 -0.8664  0.1026
    // row3:  0.0574 -0.4852 -0.1026 -0.8664

    // position (i, j0)
    const float a0_0 = dot4( 0.8664f,  0.1026f,  0.4852f, -0.0574f, A.x,  A.y,  B.x,  B.y);
    const float a1_0 = dot4(-0.1026f,  0.8664f, -0.0574f, -0.4852f, Cv.x, Cv.y, D.x,  D.y);
    const float a2_0 = dot4( 0.4852f,  0.0574f, -0.8664f,  0.1026f, A.z,  A.w,  B.z,  B.w);
    const float a3_0 = dot4( 0.0574f, -0.4852f, -0.1026f, -0.8664f, Cv.z, Cv.w, D.z,  D.w);

    // position (i, j0+1)
    const float a0_1 = dot4( 0.8664f,  0.1026f,  0.4852f, -0.0574f, A.z,  A.w,  B.z,  B.w);
    const float a1_1 = dot4(-0.1026f,  0.8664f, -0.0574f, -0.4852f, Cv.z, Cv.w, D.z,  D.w);
    const float a2_1 = dot4( 0.4852f,  0.0574f, -0.8664f,  0.1026f, A2.x, A2.y, B2.x, B2.y);
    const float a3_1 = dot4( 0.0574f, -0.4852f, -0.1026f, -0.8664f, C2.x, C2.y, D2.x, D2.y);

    // M2 rows:
    //  1.3968  0.2212 -0.2212 -1.3968
    // -0.2212  1.3968 -1.3968  0.2212
    // -0.5412 -1.3066 -1.3066 -0.5412
    //  1.3066 -0.5412 -0.5412  1.3066
    float2 o0, o1, o2, o3;
    o0.x = dot4( 1.3968f,  0.2212f, -0.2212f, -1.3968f, a0_0, a1_0, a2_0, a3_0);
    o1.x = dot4(-0.2212f,  1.3968f, -1.3968f,  0.2212f, a0_0, a1_0, a2_0, a3_0);
    o2.x = dot4(-0.5412f, -1.3066f, -1.3066f, -0.5412f, a0_0, a1_0, a2_0, a3_0);
    o3.x = dot4( 1.3066f, -0.5412f, -0.5412f,  1.3066f, a0_0, a1_0, a2_0, a3_0);
    o0.y = dot4( 1.3968f,  0.2212f, -0.2212f, -1.3968f, a0_1, a1_1, a2_1, a3_1);
    o1.y = dot4(-0.2212f,  1.3968f, -1.3968f,  0.2212f, a0_1, a1_1, a2_1, a3_1);
    o2.y = dot4(-0.5412f, -1.3066f, -1.3066f, -0.5412f, a0_1, a1_1, a2_1, a3_1);
    o3.y = dot4( 1.3066f, -0.5412f, -0.5412f,  1.3066f, a0_1, a1_1, a2_1, a3_1);

    // out[b, s*32 + c, i, j] ; bc = b*32 + c
    const int b = bc >> 5;
    const int c = bc & 31;
    const size_t sband = (size_t)Cd * H1d * W1d;                       // stride per subband
    float* op = out + ((size_t)(b * 4 * Cd + c) * H1d + i) * W1d + j0;

    // Streaming stores: outputs have zero reuse; evict-first keeps L2 for the
    // rolled input rows and drains writes aggressively.
    __stcs((float2*)(op),             o0);
    __stcs((float2*)(op + sband),     o1);
    __stcs((float2*)(op + 2 * sband), o2);
    __stcs((float2*)(op + 3 * sband), o3);
}

extern "C" void kernel_launch(void* const* d_in, const int* in_sizes, int n_in,
                              void* d_out, int out_size) {
    const float* x = (const float*)d_in[0];
    float* out = (float*)d_out;
    dim3 grid(H1d, 8 * Cd);   // (256 rows, 256 bc slices)
    nlwt_kernel<<<grid, 128>>>(x, out);
}